// round 2
// baseline (speedup 1.0000x reference)
#include <cuda_runtime.h>
#include <math.h>

#define BB   8
#define HH   96
#define WW   160
#define HW   (HH*WW)

// scratch (allocation-free rule: __device__ globals)
__device__ float g_h1[8*256*96*160];
__device__ float g_h2[8*256*96*160];
__device__ float g_u1[8*128*96*160];

// ---------------------------------------------------------------------------
// 3x3 conv (pad 1) + optional BN + ReLU.  IC multiple of 8. OC multiple of 32.
// Block: 256 threads -> tile 32 OC x 8 H x 32 W. Thread: 4 OC x 8 W.
// ---------------------------------------------------------------------------
__global__ __launch_bounds__(256) void conv3x3_bn_relu(
    const float* __restrict__ in, const float* __restrict__ wgt,
    const float* __restrict__ bias,
    const float* __restrict__ gam, const float* __restrict__ bet,
    const float* __restrict__ mu,  const float* __restrict__ var,
    float* __restrict__ out, int IC, int OC, int useBN)
{
    __shared__ float s_in[8][10][35];   // stride 35 -> conflict-free reads
    __shared__ float s_w[72][32];       // [ic*9+k][oc]

    const int tid = threadIdx.x;
    const int wt = blockIdx.x % 5, ht = blockIdx.x / 5;
    const int w0 = wt * 32, h0 = ht * 8;
    const int oc0 = blockIdx.y * 32;
    const int b = blockIdx.z;

    const int ocq = tid >> 5;           // 0..7 : oc quad
    const int pos = tid & 31;
    const int hl  = pos >> 2;           // 0..7
    const int wb  = (pos & 3) << 3;     // 0,8,16,24

    float acc[4][8];
#pragma unroll
    for (int o = 0; o < 4; o++)
#pragma unroll
        for (int w = 0; w < 8; w++) acc[o][w] = 0.f;

    for (int icc = 0; icc < IC; icc += 8) {
        // stage input 8 ic x 10 rows x 34 cols (with halo, zero padded)
        for (int e = tid; e < 8*10*34; e += 256) {
            int ic = e / 340; int rem = e - ic*340;
            int r = rem / 34; int c = rem - r*34;
            int y = h0 + r - 1, x = w0 + c - 1;
            float vv = 0.f;
            if (y >= 0 && y < HH && x >= 0 && x < WW)
                vv = in[(((size_t)b*IC + icc + ic)*HH + y)*WW + x];
            s_in[ic][r][c] = vv;
        }
        // stage weights 32 oc x (8 ic * 9) — contiguous 72 floats per oc
        for (int e = tid; e < 2304; e += 256) {
            int oc = e / 72; int r = e - oc*72;
            s_w[r][oc] = wgt[((size_t)(oc0 + oc)*IC + icc)*9 + r];
        }
        __syncthreads();

        for (int ic = 0; ic < 8; ic++) {
#pragma unroll
            for (int kh = 0; kh < 3; kh++) {
                float rr[10];
#pragma unroll
                for (int j = 0; j < 10; j++) rr[j] = s_in[ic][hl + kh][wb + j];
#pragma unroll
                for (int kw = 0; kw < 3; kw++) {
                    float wv[4];
#pragma unroll
                    for (int o = 0; o < 4; o++) wv[o] = s_w[ic*9 + kh*3 + kw][ocq*4 + o];
#pragma unroll
                    for (int o = 0; o < 4; o++)
#pragma unroll
                        for (int w = 0; w < 8; w++)
                            acc[o][w] = fmaf(wv[o], rr[w + kw], acc[o][w]);
                }
            }
        }
        __syncthreads();
    }

    const int ho = h0 + hl, wo = w0 + wb;
#pragma unroll
    for (int o = 0; o < 4; o++) {
        int oc = oc0 + ocq*4 + o;
        float sc, sh;
        if (useBN) {
            float s = gam[oc] * rsqrtf(var[oc] + 1e-5f);
            sc = s;
            sh = (bias[oc] - mu[oc]) * s + bet[oc];
        } else {
            sc = 1.f;
            sh = bias[oc];
        }
        size_t base = (((size_t)b*OC + oc)*HH + ho)*WW + wo;
#pragma unroll
        for (int w = 0; w < 8; w++) {
            float vv = acc[o][w] * sc + sh;
            out[base + w] = vv > 0.f ? vv : 0.f;
        }
    }
}

// ---------------------------------------------------------------------------
// 1x1 conv to a single channel + head nonlinearity.
// mode 0: sigmoid -> disparity -> depth.  mode 1: softplus (uncertainty).
// grid: 480 blocks x 256 threads == 122880 pixels exactly.
// ---------------------------------------------------------------------------
__global__ __launch_bounds__(256) void head1x1(
    const float* __restrict__ in, const float* __restrict__ w,
    const float* __restrict__ bias, float* __restrict__ out, int C, int mode)
{
    __shared__ float sw[256];
    if (threadIdx.x < C) sw[threadIdx.x] = w[threadIdx.x];
    __syncthreads();

    int idx = blockIdx.x * 256 + threadIdx.x;
    int b = idx / HW; int p = idx - b*HW;
    const float* base = in + (size_t)b*C*HW + p;
    float acc = bias[0];
#pragma unroll 8
    for (int c = 0; c < C; c++) acc += base[(size_t)c*HW] * sw[c];

    float res;
    if (mode == 0) {
        float disp = 1.f / (1.f + expf(-acc));
        res = 1.f / (0.01f + 9.99f * disp);   // min_disp=1/100, max_disp=1/0.1
    } else {
        res = acc > 20.f ? acc : log1pf(expf(acc));
    }
    out[idx] = res;
}

// ---------------------------------------------------------------------------
// Per-box lower median via exact 32-bit radix select (depth > 0 => uint order
// preserving). One block per (b, n). rank = (k-1)/2.
// ---------------------------------------------------------------------------
__global__ __launch_bounds__(256) void box_median(
    const float* __restrict__ depth, const int* __restrict__ bboxes,
    float* __restrict__ out)
{
    const int bi = blockIdx.x;           // 0..511
    const int b = bi >> 6;
    const int tid = threadIdx.x;
    const int* box = bboxes + (size_t)bi * 4;

    int x1 = max(box[0], 0), y1 = max(box[1], 0);
    int x2 = min(box[2], WW), y2 = min(box[3], HH);
    int wdt = x2 - x1, hgt = y2 - y1;
    if (wdt <= 0 || hgt <= 0) {
        if (tid == 0) out[bi] = 0.f;
        return;
    }
    const int k = wdt * hgt;
    int r = (k - 1) >> 1;

    __shared__ unsigned hist[256];
    const float* dimg = depth + (size_t)b * HW;
    unsigned prefix = 0;

    for (int pass = 0; pass < 4; ++pass) {
        int shift = 24 - 8*pass;
        hist[tid] = 0;
        __syncthreads();
        unsigned pmask = (pass == 0) ? 0u : (0xFFFFFFFFu << (shift + 8));
        for (int e = tid; e < k; e += 256) {
            int y = y1 + e / wdt, x = x1 + e % wdt;
            unsigned bits = __float_as_uint(dimg[y*WW + x]);
            if ((bits & pmask) == prefix)
                atomicAdd(&hist[(bits >> shift) & 0xFF], 1u);
        }
        __syncthreads();
        // all threads scan identically (broadcast reads, uniform result)
        unsigned cum = 0; int bin = -1;
        for (int i = 0; i < 256; i++) {
            unsigned h = hist[i];
            if (bin < 0 && r < (int)(cum + h)) { bin = i; r -= (int)cum; }
            cum += h;
        }
        prefix |= ((unsigned)bin) << shift;
        __syncthreads();   // protect hist before next pass reset
    }
    if (tid == 0) out[bi] = __uint_as_float(prefix);
}

// ---------------------------------------------------------------------------
extern "C" void kernel_launch(void* const* d_in, const int* in_sizes, int n_in,
                              void* d_out, int out_size)
{
    const float* features = (const float*)d_in[0];
    const int*   bboxes   = (const int*)  d_in[1];
    const float* w1  = (const float*)d_in[2];
    const float* b1  = (const float*)d_in[3];
    const float* g1  = (const float*)d_in[4];
    const float* be1 = (const float*)d_in[5];
    const float* m1  = (const float*)d_in[6];
    const float* v1  = (const float*)d_in[7];
    const float* w2  = (const float*)d_in[8];
    const float* b2  = (const float*)d_in[9];
    const float* g2  = (const float*)d_in[10];
    const float* be2 = (const float*)d_in[11];
    const float* m2  = (const float*)d_in[12];
    const float* v2  = (const float*)d_in[13];
    const float* w3  = (const float*)d_in[14];
    const float* b3  = (const float*)d_in[15];
    const float* uw1 = (const float*)d_in[16];
    const float* ub1 = (const float*)d_in[17];
    const float* uw2 = (const float*)d_in[18];
    const float* ub2 = (const float*)d_in[19];

    float* out = (float*)d_out;

    float *h1, *h2, *u1;
    cudaGetSymbolAddress((void**)&h1, g_h1);
    cudaGetSymbolAddress((void**)&h2, g_h2);
    cudaGetSymbolAddress((void**)&u1, g_u1);

    dim3 cgrid(60, 8, 8);    // 5 Wtiles * 12 Htiles, 8 oc-tiles, 8 batch
    dim3 ugrid(60, 4, 8);

    // depth head
    conv3x3_bn_relu<<<cgrid, 256>>>(features, w1, b1, g1, be1, m1, v1, h1, 256, 256, 1);
    conv3x3_bn_relu<<<cgrid, 256>>>(h1,       w2, b2, g2, be2, m2, v2, h2, 256, 256, 1);
    head1x1<<<480, 256>>>(h2, w3, b3, out, 256, 0);                 // depth -> out[0:122880)

    // uncertainty head
    conv3x3_bn_relu<<<ugrid, 256>>>(features, uw1, ub1, nullptr, nullptr, nullptr, nullptr,
                                    u1, 256, 128, 0);
    head1x1<<<480, 256>>>(u1, uw2, ub2, out + 122880, 128, 1);      // unc -> out[122880:245760)

    // per-box medians from depth
    box_median<<<512, 256>>>(out, bboxes, out + 245760);            // obj -> out[245760:246272)
}

// round 5
// speedup vs baseline: 2.2642x; 2.2642x over previous
#include <cuda_runtime.h>
#include <math.h>
#include <stdint.h>

#define HH 96
#define WW 160
#define HW (HH*WW)
#define ICC 256

// scratch (allocation-free rule: __device__ globals)
__device__ float g_h1[8*256*96*160];
__device__ float g_h2[8*256*96*160];
__device__ float g_u1[8*128*96*160];
__device__ float g_w1t[9*256*256];
__device__ float g_w2t[9*256*256];
__device__ float g_uwt[9*256*128];

__device__ __forceinline__ uint32_t f2tf32(float x){
    uint32_t u;
    asm("cvt.rna.tf32.f32 %0, %1;" : "=r"(u) : "f"(x));
    return u;
}
__device__ __forceinline__ void mma_tf32(float* d, const uint32_t* a, const uint32_t* b){
    asm volatile(
        "mma.sync.aligned.m16n8k8.row.col.f32.tf32.tf32.f32 "
        "{%0,%1,%2,%3}, {%4,%5,%6,%7}, {%8,%9}, {%0,%1,%2,%3};"
        : "+f"(d[0]), "+f"(d[1]), "+f"(d[2]), "+f"(d[3])
        : "r"(a[0]), "r"(a[1]), "r"(a[2]), "r"(a[3]), "r"(b[0]), "r"(b[1]));
}

// ---------------------------------------------------------------------------
// Weight transform: w[oc][ic][kh][kw] -> wt[t][ic][oc]   (t = kh*3+kw)
// ---------------------------------------------------------------------------
__global__ void wtrans(const float* __restrict__ w, float* __restrict__ wt, int OC){
    int e = blockIdx.x * 256 + threadIdx.x;
    int total = 9 * 256 * OC;
    if (e >= total) return;
    int oc = e % OC;
    int ic = (e / OC) % 256;
    int t  = e / (OC * 256);
    wt[e] = w[((size_t)oc * 256 + ic) * 9 + t];
}

// ---------------------------------------------------------------------------
// tf32 mma.sync implicit-GEMM conv3x3 (pad 1) + BN/bias + ReLU.
// CTA: M=128 oc x N=128 flat pixels. K = 9 taps * 256 ic, chunks of 16.
// 8 warps: warp tile 64(M) x 32(N). Software-pipelined smem double buffer.
// ---------------------------------------------------------------------------
__global__ __launch_bounds__(256, 1) void conv3x3_mma(
    const float* __restrict__ in, const float* __restrict__ wt,
    const float* __restrict__ bias, const float* __restrict__ gam,
    const float* __restrict__ bet, const float* __restrict__ mu,
    const float* __restrict__ var, float* __restrict__ out,
    int OC, int useBN)
{
    __shared__ uint32_t a_s[2][16][132];
    __shared__ uint32_t b_s[2][16][132];
    __shared__ float sc_s[128], sh_s[128];

    const int tid = threadIdx.x;
    const int wid = tid >> 5, lane = tid & 31;
    const int b = blockIdx.z;
    const int px0 = blockIdx.x * 128;
    const int oc0 = blockIdx.y * 128;

    // BN fold table
    if (tid < 128) {
        int oc = oc0 + tid;
        if (useBN) {
            float s = gam[oc] * rsqrtf(var[oc] + 1e-5f);
            sc_s[tid] = s;
            sh_s[tid] = (bias[oc] - mu[oc]) * s + bet[oc];
        } else {
            sc_s[tid] = 1.f;
            sh_s[tid] = bias[oc];
        }
    }

    // per-thread staging geometry (loop-invariant)
    const int j   = tid & 127;       // pixel column within tile / oc column
    const int khi = tid >> 7;        // 0/1 -> k parity base
    const int p   = px0 + j;
    const int y   = p / WW, x = p - (p / WW) * WW;

    // warp tile origin
    const int m0w = (wid & 1) * 64;
    const int n0w = (wid >> 1) * 32;
    const int lg  = lane >> 2;       // group id 0..7
    const int lt  = lane & 3;        // thread-in-group 0..3

    float d[4][4][4];
    #pragma unroll
    for (int mt = 0; mt < 4; mt++)
        #pragma unroll
        for (int nt = 0; nt < 4; nt++)
            #pragma unroll
            for (int q = 0; q < 4; q++) d[mt][nt][q] = 0.f;

    float ra[8], rb[8];

    // prologue: load chunk 0  (tap 0 => kh=0, kw=0)
    {
        const float* ap = wt + (size_t)khi*OC + oc0 + j;
        #pragma unroll
        for (int i = 0; i < 8; i++) ra[i] = ap[(size_t)(2*i)*OC];
        int yy = y - 1, xx = x - 1;
        bool ok = ((unsigned)yy < HH) && ((unsigned)xx < WW);
        const float* bp = in + ((size_t)(b*ICC + khi)*HH + yy)*WW + xx;
        #pragma unroll
        for (int i = 0; i < 8; i++) rb[i] = ok ? bp[(size_t)(2*i)*HW] : 0.f;
    }

    for (int c = 0; c < 144; c++) {
        const int pb = c & 1;
        // store staged regs
        #pragma unroll
        for (int i = 0; i < 8; i++) {
            a_s[pb][2*i + khi][j] = f2tf32(ra[i]);
            b_s[pb][2*i + khi][j] = f2tf32(rb[i]);
        }
        __syncthreads();

        // issue loads for next chunk
        if (c + 1 < 144) {
            const int cn = c + 1;
            const int t = cn >> 4, icc = (cn & 15) << 4;
            const int kh = (t * 11) >> 5;            // t/3 for t in [0,8]
            const int kw = t - kh*3;
            const float* ap = wt + ((size_t)(t*256 + icc + khi))*OC + oc0 + j;
            #pragma unroll
            for (int i = 0; i < 8; i++) ra[i] = ap[(size_t)(2*i)*OC];
            int yy = y + kh - 1, xx = x + kw - 1;
            bool ok = ((unsigned)yy < HH) && ((unsigned)xx < WW);
            const float* bp = in + ((size_t)(b*ICC + icc + khi)*HH + yy)*WW + xx;
            #pragma unroll
            for (int i = 0; i < 8; i++) rb[i] = ok ? bp[(size_t)(2*i)*HW] : 0.f;
        }

        // compute on buffer pb: 2 k-steps of 8
        #pragma unroll
        for (int ks = 0; ks < 2; ks++) {
            const int k0 = ks * 8;
            uint32_t af[4][4], bf[4][2];
            #pragma unroll
            for (int mt = 0; mt < 4; mt++) {
                int mrow = m0w + mt*16 + lg;
                af[mt][0] = a_s[pb][k0 + lt    ][mrow    ];
                af[mt][1] = a_s[pb][k0 + lt    ][mrow + 8];
                af[mt][2] = a_s[pb][k0 + 4 + lt][mrow    ];
                af[mt][3] = a_s[pb][k0 + 4 + lt][mrow + 8];
            }
            #pragma unroll
            for (int nt = 0; nt < 4; nt++) {
                int ncol = n0w + nt*8 + lg;
                bf[nt][0] = b_s[pb][k0 + lt    ][ncol];
                bf[nt][1] = b_s[pb][k0 + 4 + lt][ncol];
            }
            #pragma unroll
            for (int mt = 0; mt < 4; mt++)
                #pragma unroll
                for (int nt = 0; nt < 4; nt++)
                    mma_tf32(d[mt][nt], af[mt], bf[nt]);
        }
    }
    __syncthreads();

    // epilogue: BN + ReLU + store
    #pragma unroll
    for (int mt = 0; mt < 4; mt++) {
        int r0 = m0w + mt*16 + lg;
        float sc0 = sc_s[r0],     sh0 = sh_s[r0];
        float sc1 = sc_s[r0 + 8], sh1 = sh_s[r0 + 8];
        float* ob0 = out + ((size_t)(b*OC + oc0 + r0    ) * HW) + px0;
        float* ob1 = out + ((size_t)(b*OC + oc0 + r0 + 8) * HW) + px0;
        #pragma unroll
        for (int nt = 0; nt < 4; nt++) {
            int cc = n0w + nt*8 + lt*2;
            float v0 = d[mt][nt][0] * sc0 + sh0;
            float v1 = d[mt][nt][1] * sc0 + sh0;
            float v2 = d[mt][nt][2] * sc1 + sh1;
            float v3 = d[mt][nt][3] * sc1 + sh1;
            *(float2*)(ob0 + cc) = make_float2(v0 > 0.f ? v0 : 0.f, v1 > 0.f ? v1 : 0.f);
            *(float2*)(ob1 + cc) = make_float2(v2 > 0.f ? v2 : 0.f, v3 > 0.f ? v3 : 0.f);
        }
    }
}

// ---------------------------------------------------------------------------
// 1x1 conv to one channel + head nonlinearity (mode 0: depth, 1: softplus)
// ---------------------------------------------------------------------------
__global__ __launch_bounds__(256) void head1x1(
    const float* __restrict__ in, const float* __restrict__ w,
    const float* __restrict__ bias, float* __restrict__ out, int C, int mode)
{
    __shared__ float sw[256];
    if (threadIdx.x < C) sw[threadIdx.x] = w[threadIdx.x];
    __syncthreads();

    int idx = blockIdx.x * 256 + threadIdx.x;
    int b = idx / HW; int p = idx - b*HW;
    const float* base = in + (size_t)b*C*HW + p;
    float acc = bias[0];
#pragma unroll 8
    for (int c = 0; c < C; c++) acc += base[(size_t)c*HW] * sw[c];

    float res;
    if (mode == 0) {
        float disp = 1.f / (1.f + expf(-acc));
        res = 1.f / (0.01f + 9.99f * disp);
    } else {
        res = acc > 20.f ? acc : log1pf(expf(acc));
    }
    out[idx] = res;
}

// ---------------------------------------------------------------------------
// Per-box lower median via exact 32-bit radix select.
// ---------------------------------------------------------------------------
__global__ __launch_bounds__(256) void box_median(
    const float* __restrict__ depth, const int* __restrict__ bboxes,
    float* __restrict__ out)
{
    const int bi = blockIdx.x;
    const int b = bi >> 6;
    const int tid = threadIdx.x;
    const int* box = bboxes + (size_t)bi * 4;

    int x1 = max(box[0], 0), y1 = max(box[1], 0);
    int x2 = min(box[2], WW), y2 = min(box[3], HH);
    int wdt = x2 - x1, hgt = y2 - y1;
    if (wdt <= 0 || hgt <= 0) {
        if (tid == 0) out[bi] = 0.f;
        return;
    }
    const int k = wdt * hgt;
    int r = (k - 1) >> 1;

    __shared__ unsigned hist[256];
    const float* dimg = depth + (size_t)b * HW;
    unsigned prefix = 0;

    for (int pass = 0; pass < 4; ++pass) {
        int shift = 24 - 8*pass;
        hist[tid] = 0;
        __syncthreads();
        unsigned pmask = (pass == 0) ? 0u : (0xFFFFFFFFu << (shift + 8));
        for (int e = tid; e < k; e += 256) {
            int y = y1 + e / wdt, x = x1 + e % wdt;
            unsigned bits = __float_as_uint(dimg[y*WW + x]);
            if ((bits & pmask) == prefix)
                atomicAdd(&hist[(bits >> shift) & 0xFF], 1u);
        }
        __syncthreads();
        unsigned cum = 0; int bin = -1;
        for (int i = 0; i < 256; i++) {
            unsigned h = hist[i];
            if (bin < 0 && r < (int)(cum + h)) { bin = i; r -= (int)cum; }
            cum += h;
        }
        prefix |= ((unsigned)bin) << shift;
        __syncthreads();
    }
    if (tid == 0) out[bi] = __uint_as_float(prefix);
}

// ---------------------------------------------------------------------------
extern "C" void kernel_launch(void* const* d_in, const int* in_sizes, int n_in,
                              void* d_out, int out_size)
{
    const float* features = (const float*)d_in[0];
    const int*   bboxes   = (const int*)  d_in[1];
    const float* w1  = (const float*)d_in[2];
    const float* b1  = (const float*)d_in[3];
    const float* g1  = (const float*)d_in[4];
    const float* be1 = (const float*)d_in[5];
    const float* m1  = (const float*)d_in[6];
    const float* v1  = (const float*)d_in[7];
    const float* w2  = (const float*)d_in[8];
    const float* b2  = (const float*)d_in[9];
    const float* g2  = (const float*)d_in[10];
    const float* be2 = (const float*)d_in[11];
    const float* m2  = (const float*)d_in[12];
    const float* v2  = (const float*)d_in[13];
    const float* w3  = (const float*)d_in[14];
    const float* b3  = (const float*)d_in[15];
    const float* uw1 = (const float*)d_in[16];
    const float* ub1 = (const float*)d_in[17];
    const float* uw2 = (const float*)d_in[18];
    const float* ub2 = (const float*)d_in[19];

    float* out = (float*)d_out;

    float *h1, *h2, *u1, *w1t, *w2t, *uwt;
    cudaGetSymbolAddress((void**)&h1,  g_h1);
    cudaGetSymbolAddress((void**)&h2,  g_h2);
    cudaGetSymbolAddress((void**)&u1,  g_u1);
    cudaGetSymbolAddress((void**)&w1t, g_w1t);
    cudaGetSymbolAddress((void**)&w2t, g_w2t);
    cudaGetSymbolAddress((void**)&uwt, g_uwt);

    // weight layout transforms
    wtrans<<<(9*256*256 + 255)/256, 256>>>(w1,  w1t, 256);
    wtrans<<<(9*256*256 + 255)/256, 256>>>(w2,  w2t, 256);
    wtrans<<<(9*256*128 + 255)/256, 256>>>(uw1, uwt, 128);

    dim3 g256(120, 2, 8);   // 120 pixel tiles, 2 oc-tiles, 8 batch
    dim3 g128(120, 1, 8);

    // depth head
    conv3x3_mma<<<g256, 256>>>(features, w1t, b1, g1, be1, m1, v1, h1, 256, 1);
    conv3x3_mma<<<g256, 256>>>(h1,       w2t, b2, g2, be2, m2, v2, h2, 256, 1);
    head1x1<<<480, 256>>>(h2, w3, b3, out, 256, 0);                 // depth

    // uncertainty head
    conv3x3_mma<<<g128, 256>>>(features, uwt, ub1,
        (const float*)0, (const float*)0, (const float*)0, (const float*)0, u1, 128, 0);
    head1x1<<<480, 256>>>(u1, uw2, ub2, out + 122880, 128, 1);      // uncertainty

    // per-box medians from depth
    box_median<<<512, 256>>>(out, bboxes, out + 245760);            // obj depths
}

// round 6
// speedup vs baseline: 3.8384x; 1.6953x over previous
#include <cuda_runtime.h>
#include <math.h>
#include <stdint.h>

#define HH 96
#define WW 160
#define HW (HH*WW)
#define ICC 256

// scratch (allocation-free rule: __device__ globals)
__device__ float g_h1[8*256*96*160];
__device__ float g_h2[8*256*96*160];
__device__ float g_u1[8*128*96*160];
__device__ float g_w1t[9*256*256];
__device__ float g_w2t[9*256*256];
__device__ float g_uwt[9*256*128];

__device__ __forceinline__ void mma_tf32(float* d, const uint32_t* a, const uint32_t* b){
    asm volatile(
        "mma.sync.aligned.m16n8k8.row.col.f32.tf32.tf32.f32 "
        "{%0,%1,%2,%3}, {%4,%5,%6,%7}, {%8,%9}, {%0,%1,%2,%3};"
        : "+f"(d[0]), "+f"(d[1]), "+f"(d[2]), "+f"(d[3])
        : "r"(a[0]), "r"(a[1]), "r"(a[2]), "r"(a[3]), "r"(b[0]), "r"(b[1]));
}
__device__ __forceinline__ void cp16(uint32_t smem_dst, const void* gptr){
    asm volatile("cp.async.cg.shared.global [%0], [%1], 16;" :: "r"(smem_dst), "l"(gptr));
}
__device__ __forceinline__ void cp_commit(){ asm volatile("cp.async.commit_group;"); }
__device__ __forceinline__ void cp_wait0(){ asm volatile("cp.async.wait_group 0;"); }

// ---------------------------------------------------------------------------
// Weight transform: w[oc][ic][kh][kw] -> wt[t][ic][oc]   (t = kh*3+kw)
// ---------------------------------------------------------------------------
__global__ void wtrans(const float* __restrict__ w, float* __restrict__ wt, int OC){
    int e = blockIdx.x * 256 + threadIdx.x;
    int total = 9 * 256 * OC;
    if (e >= total) return;
    int oc = e % OC;
    int ic = (e / OC) % 256;
    int t  = e / (OC * 256);
    wt[e] = w[((size_t)oc * 256 + ic) * 9 + t];
}

// ---------------------------------------------------------------------------
// tf32 mma.sync implicit-GEMM conv3x3 (pad 1) + BN/bias + ReLU.
// CTA: M=128 oc x N=128 flat pixels. K = 9 taps * 256 ic, chunks of 16.
// A staged via cp.async (no halo), B via predicated LDG->STS, double buffered.
// Raw f32 bits fed to tf32 MMA (HW truncates mantissa; no cvt needed).
// ---------------------------------------------------------------------------
__global__ __launch_bounds__(256, 2) void conv3x3_mma(
    const float* __restrict__ in, const float* __restrict__ wt,
    const float* __restrict__ bias, const float* __restrict__ gam,
    const float* __restrict__ bet, const float* __restrict__ mu,
    const float* __restrict__ var, float* __restrict__ out,
    int OC, int useBN)
{
    __shared__ uint32_t a_s[2][16][136];   // stride 136 -> conflict-free frags
    __shared__ uint32_t b_s[2][16][136];
    __shared__ float sc_s[128], sh_s[128];

    const int tid = threadIdx.x;
    const int wid = tid >> 5, lane = tid & 31;
    const int b = blockIdx.z;
    const int px0 = blockIdx.x * 128;
    const int oc0 = blockIdx.y * 128;

    // BN fold table
    if (tid < 128) {
        int oc = oc0 + tid;
        if (useBN) {
            float s = gam[oc] * rsqrtf(var[oc] + 1e-5f);
            sc_s[tid] = s;
            sh_s[tid] = (bias[oc] - mu[oc]) * s + bet[oc];
        } else {
            sc_s[tid] = 1.f;
            sh_s[tid] = bias[oc];
        }
    }

    // per-thread B staging geometry (loop-invariant)
    const int j   = tid & 127;       // pixel column within tile
    const int khi = tid >> 7;        // 0/1 -> k parity base
    const int p   = px0 + j;
    const int y   = p / WW, x = p - (p / WW) * WW;

    // per-thread A cp.async geometry: 2 x 16B per thread per chunk
    const int arow = tid >> 4;          // 0..15 (k row)
    const int acol = (tid & 15) * 8;    // float offset; 2 segs of 4 floats
    uint32_t a_dst0[2], a_dst1[2];
    #pragma unroll
    for (int pp = 0; pp < 2; pp++) {
        a_dst0[pp] = (uint32_t)__cvta_generic_to_shared(&a_s[pp][arow][acol]);
        a_dst1[pp] = a_dst0[pp] + 16;
    }

    // warp tile origin
    const int m0w = (wid & 1) * 64;
    const int n0w = (wid >> 1) * 32;
    const int lg  = lane >> 2;       // group id 0..7
    const int lt  = lane & 3;        // thread-in-group 0..3

    float d[4][4][4];
    #pragma unroll
    for (int mt = 0; mt < 4; mt++)
        #pragma unroll
        for (int nt = 0; nt < 4; nt++)
            #pragma unroll
            for (int q = 0; q < 4; q++) d[mt][nt][q] = 0.f;

    float rb[8];

    // prologue: A(0) via cp.async, B(0) via LDG
    {
        const float* ap = wt + (size_t)arow * OC + oc0 + acol;
        cp16(a_dst0[0], ap);
        cp16(a_dst1[0], ap + 4);
        cp_commit();

        int yy = y - 1, xx = x - 1;
        bool ok = ((unsigned)yy < HH) && ((unsigned)xx < WW);
        const float* bp = in + ((size_t)(b*ICC + khi)*HH + yy)*WW + xx;
        #pragma unroll
        for (int i = 0; i < 8; i++) rb[i] = ok ? bp[(size_t)(2*i)*HW] : 0.f;
    }

    for (int c = 0; c < 144; c++) {
        const int pb = c & 1;
        // store staged B regs (raw f32 bits)
        #pragma unroll
        for (int i = 0; i < 8; i++)
            b_s[pb][2*i + khi][j] = __float_as_uint(rb[i]);

        cp_wait0();          // A(c) resident
        __syncthreads();     // A(c)+B(c) visible; all warps done mma(c-1)

        // issue next chunk's loads
        if (c + 1 < 144) {
            const int cn = c + 1;
            const int t = cn >> 4, icc = (cn & 15) << 4;
            const int kh = (t * 11) >> 5;            // t/3 for t in [0,8]
            const int kw = t - kh*3;

            const float* ap = wt + ((size_t)(t*256 + icc + arow))*OC + oc0 + acol;
            cp16(a_dst0[pb^1], ap);
            cp16(a_dst1[pb^1], ap + 4);
            cp_commit();

            int yy = y + kh - 1, xx = x + kw - 1;
            bool ok = ((unsigned)yy < HH) && ((unsigned)xx < WW);
            const float* bp = in + ((size_t)(b*ICC + icc + khi)*HH + yy)*WW + xx;
            #pragma unroll
            for (int i = 0; i < 8; i++) rb[i] = ok ? bp[(size_t)(2*i)*HW] : 0.f;
        }

        // compute on buffer pb: 2 k-steps of 8
        #pragma unroll
        for (int ks = 0; ks < 2; ks++) {
            const int k0 = ks * 8;
            uint32_t af[4][4], bf[4][2];
            #pragma unroll
            for (int mt = 0; mt < 4; mt++) {
                int mrow = m0w + mt*16 + lg;
                af[mt][0] = a_s[pb][k0 + lt    ][mrow    ];
                af[mt][1] = a_s[pb][k0 + lt    ][mrow + 8];
                af[mt][2] = a_s[pb][k0 + 4 + lt][mrow    ];
                af[mt][3] = a_s[pb][k0 + 4 + lt][mrow + 8];
            }
            #pragma unroll
            for (int nt = 0; nt < 4; nt++) {
                int ncol = n0w + nt*8 + lg;
                bf[nt][0] = b_s[pb][k0 + lt    ][ncol];
                bf[nt][1] = b_s[pb][k0 + 4 + lt][ncol];
            }
            #pragma unroll
            for (int mt = 0; mt < 4; mt++)
                #pragma unroll
                for (int nt = 0; nt < 4; nt++)
                    mma_tf32(d[mt][nt], af[mt], bf[nt]);
        }
    }
    __syncthreads();

    // epilogue: BN + ReLU + store
    #pragma unroll
    for (int mt = 0; mt < 4; mt++) {
        int r0 = m0w + mt*16 + lg;
        float sc0 = sc_s[r0],     sh0 = sh_s[r0];
        float sc1 = sc_s[r0 + 8], sh1 = sh_s[r0 + 8];
        float* ob0 = out + ((size_t)(b*OC + oc0 + r0    ) * HW) + px0;
        float* ob1 = out + ((size_t)(b*OC + oc0 + r0 + 8) * HW) + px0;
        #pragma unroll
        for (int nt = 0; nt < 4; nt++) {
            int cc = n0w + nt*8 + lt*2;
            float v0 = d[mt][nt][0] * sc0 + sh0;
            float v1 = d[mt][nt][1] * sc0 + sh0;
            float v2 = d[mt][nt][2] * sc1 + sh1;
            float v3 = d[mt][nt][3] * sc1 + sh1;
            *(float2*)(ob0 + cc) = make_float2(v0 > 0.f ? v0 : 0.f, v1 > 0.f ? v1 : 0.f);
            *(float2*)(ob1 + cc) = make_float2(v2 > 0.f ? v2 : 0.f, v3 > 0.f ? v3 : 0.f);
        }
    }
}

// ---------------------------------------------------------------------------
// 1x1 conv to one channel + head nonlinearity (mode 0: depth, 1: softplus)
// ---------------------------------------------------------------------------
__global__ __launch_bounds__(256) void head1x1(
    const float* __restrict__ in, const float* __restrict__ w,
    const float* __restrict__ bias, float* __restrict__ out, int C, int mode)
{
    __shared__ float sw[256];
    if (threadIdx.x < C) sw[threadIdx.x] = w[threadIdx.x];
    __syncthreads();

    int idx = blockIdx.x * 256 + threadIdx.x;
    int b = idx / HW; int p = idx - b*HW;
    const float* base = in + (size_t)b*C*HW + p;
    float acc = bias[0];
#pragma unroll 8
    for (int c = 0; c < C; c++) acc += base[(size_t)c*HW] * sw[c];

    float res;
    if (mode == 0) {
        float disp = 1.f / (1.f + expf(-acc));
        res = 1.f / (0.01f + 9.99f * disp);
    } else {
        res = acc > 20.f ? acc : log1pf(expf(acc));
    }
    out[idx] = res;
}

// ---------------------------------------------------------------------------
// Per-box lower median via exact 32-bit radix select.
// ---------------------------------------------------------------------------
__global__ __launch_bounds__(256) void box_median(
    const float* __restrict__ depth, const int* __restrict__ bboxes,
    float* __restrict__ out)
{
    const int bi = blockIdx.x;
    const int b = bi >> 6;
    const int tid = threadIdx.x;
    const int* box = bboxes + (size_t)bi * 4;

    int x1 = max(box[0], 0), y1 = max(box[1], 0);
    int x2 = min(box[2], WW), y2 = min(box[3], HH);
    int wdt = x2 - x1, hgt = y2 - y1;
    if (wdt <= 0 || hgt <= 0) {
        if (tid == 0) out[bi] = 0.f;
        return;
    }
    const int k = wdt * hgt;
    int r = (k - 1) >> 1;

    __shared__ unsigned hist[256];
    const float* dimg = depth + (size_t)b * HW;
    unsigned prefix = 0;

    for (int pass = 0; pass < 4; ++pass) {
        int shift = 24 - 8*pass;
        hist[tid] = 0;
        __syncthreads();
        unsigned pmask = (pass == 0) ? 0u : (0xFFFFFFFFu << (shift + 8));
        for (int e = tid; e < k; e += 256) {
            int y = y1 + e / wdt, x = x1 + e % wdt;
            unsigned bits = __float_as_uint(dimg[y*WW + x]);
            if ((bits & pmask) == prefix)
                atomicAdd(&hist[(bits >> shift) & 0xFF], 1u);
        }
        __syncthreads();
        unsigned cum = 0; int bin = -1;
        for (int i = 0; i < 256; i++) {
            unsigned h = hist[i];
            if (bin < 0 && r < (int)(cum + h)) { bin = i; r -= (int)cum; }
            cum += h;
        }
        prefix |= ((unsigned)bin) << shift;
        __syncthreads();
    }
    if (tid == 0) out[bi] = __uint_as_float(prefix);
}

// ---------------------------------------------------------------------------
extern "C" void kernel_launch(void* const* d_in, const int* in_sizes, int n_in,
                              void* d_out, int out_size)
{
    const float* features = (const float*)d_in[0];
    const int*   bboxes   = (const int*)  d_in[1];
    const float* w1  = (const float*)d_in[2];
    const float* b1  = (const float*)d_in[3];
    const float* g1  = (const float*)d_in[4];
    const float* be1 = (const float*)d_in[5];
    const float* m1  = (const float*)d_in[6];
    const float* v1  = (const float*)d_in[7];
    const float* w2  = (const float*)d_in[8];
    const float* b2  = (const float*)d_in[9];
    const float* g2  = (const float*)d_in[10];
    const float* be2 = (const float*)d_in[11];
    const float* m2  = (const float*)d_in[12];
    const float* v2  = (const float*)d_in[13];
    const float* w3  = (const float*)d_in[14];
    const float* b3  = (const float*)d_in[15];
    const float* uw1 = (const float*)d_in[16];
    const float* ub1 = (const float*)d_in[17];
    const float* uw2 = (const float*)d_in[18];
    const float* ub2 = (const float*)d_in[19];

    float* out = (float*)d_out;

    float *h1, *h2, *u1, *w1t, *w2t, *uwt;
    cudaGetSymbolAddress((void**)&h1,  g_h1);
    cudaGetSymbolAddress((void**)&h2,  g_h2);
    cudaGetSymbolAddress((void**)&u1,  g_u1);
    cudaGetSymbolAddress((void**)&w1t, g_w1t);
    cudaGetSymbolAddress((void**)&w2t, g_w2t);
    cudaGetSymbolAddress((void**)&uwt, g_uwt);

    // weight layout transforms
    wtrans<<<(9*256*256 + 255)/256, 256>>>(w1,  w1t, 256);
    wtrans<<<(9*256*256 + 255)/256, 256>>>(w2,  w2t, 256);
    wtrans<<<(9*256*128 + 255)/256, 256>>>(uw1, uwt, 128);

    dim3 g256(120, 2, 8);   // 120 pixel tiles, 2 oc-tiles, 8 batch
    dim3 g128(120, 1, 8);

    // depth head
    conv3x3_mma<<<g256, 256>>>(features, w1t, b1, g1, be1, m1, v1, h1, 256, 1);
    conv3x3_mma<<<g256, 256>>>(h1,       w2t, b2, g2, be2, m2, v2, h2, 256, 1);
    head1x1<<<480, 256>>>(h2, w3, b3, out, 256, 0);                 // depth

    // uncertainty head
    conv3x3_mma<<<g128, 256>>>(features, uwt, ub1,
        (const float*)0, (const float*)0, (const float*)0, (const float*)0, u1, 128, 0);
    head1x1<<<480, 256>>>(u1, uw2, ub2, out + 122880, 128, 1);      // uncertainty

    // per-box medians from depth
    box_median<<<512, 256>>>(out, bboxes, out + 245760);            // obj depths
}

// round 7
// speedup vs baseline: 4.0914x; 1.0659x over previous
#include <cuda_runtime.h>
#include <math.h>
#include <stdint.h>

#define HH 96
#define WW 160
#define HW (HH*WW)
#define ICC 256
#define NTOT (8*ICC*HW)          // elements in conv input tensor (always 8 x 256 x HW)

// scratch (allocation-free rule: __device__ globals)
__device__ float g_h1[8*256*96*160];
__device__ float g_h2[8*256*96*160];
__device__ float g_u1[8*128*96*160];
__device__ float g_w1t[9*256*256];
__device__ float g_w2t[9*256*256];
__device__ float g_uwt[9*256*128];

__device__ __forceinline__ void mma_tf32(float* d, const uint32_t* a, const uint32_t* b){
    asm volatile(
        "mma.sync.aligned.m16n8k8.row.col.f32.tf32.tf32.f32 "
        "{%0,%1,%2,%3}, {%4,%5,%6,%7}, {%8,%9}, {%0,%1,%2,%3};"
        : "+f"(d[0]), "+f"(d[1]), "+f"(d[2]), "+f"(d[3])
        : "r"(a[0]), "r"(a[1]), "r"(a[2]), "r"(a[3]), "r"(b[0]), "r"(b[1]));
}
__device__ __forceinline__ void cp16(uint32_t smem_dst, const void* gptr){
    asm volatile("cp.async.cg.shared.global [%0], [%1], 16;" :: "r"(smem_dst), "l"(gptr));
}
__device__ __forceinline__ void cp4(uint32_t smem_dst, const void* gptr){
    asm volatile("cp.async.ca.shared.global [%0], [%1], 4;" :: "r"(smem_dst), "l"(gptr));
}
__device__ __forceinline__ void cp_commit(){ asm volatile("cp.async.commit_group;"); }

// stage layout (words): A 16x136 = 2176, B 16x136 = 2176 -> 4352 words/stage
#define STG_W 4352
#define B_OFF 2176
#define SMEM_DYN (4*STG_W*4)     // 69632 bytes

// ---------------------------------------------------------------------------
// Weight transform: w[oc][ic][kh][kw] -> wt[t][ic][oc]   (t = kh*3+kw)
// ---------------------------------------------------------------------------
__global__ void wtrans(const float* __restrict__ w, float* __restrict__ wt, int OC){
    int e = blockIdx.x * 256 + threadIdx.x;
    int total = 9 * 256 * OC;
    if (e >= total) return;
    int oc = e % OC;
    int ic = (e / OC) % 256;
    int t  = e / (OC * 256);
    wt[e] = w[((size_t)oc * 256 + ic) * 9 + t];
}

// ---------------------------------------------------------------------------
// tf32 mma.sync implicit-GEMM conv3x3 (pad 1) + BN/bias + ReLU.
// CTA: M=128 oc x N=128 flat pixels. K = 9 taps * 256 ic, chunks of 16.
// 4-stage cp.async pipeline (A via cp16, B via cp4 with linear shifted
// addresses); halo correctness via in-register masking of B fragments.
// ---------------------------------------------------------------------------
__global__ __launch_bounds__(256, 2) void conv3x3_mma(
    const float* __restrict__ in, const float* __restrict__ wt,
    const float* __restrict__ bias, const float* __restrict__ gam,
    const float* __restrict__ bet, const float* __restrict__ mu,
    const float* __restrict__ var, float* __restrict__ out,
    int OC, int useBN)
{
    extern __shared__ uint32_t sdyn[];
    __shared__ float sc_s[128], sh_s[128];

    const int tid = threadIdx.x;
    const int wid = tid >> 5, lane = tid & 31;
    const int b = blockIdx.z;
    const int px0 = blockIdx.x * 128;
    const int oc0 = blockIdx.y * 128;

    // BN fold table
    if (tid < 128) {
        int oc = oc0 + tid;
        if (useBN) {
            float s = gam[oc] * rsqrtf(var[oc] + 1e-5f);
            sc_s[tid] = s;
            sh_s[tid] = (bias[oc] - mu[oc]) * s + bet[oc];
        } else {
            sc_s[tid] = 1.f;
            sh_s[tid] = bias[oc];
        }
    }

    const uint32_t sbase = (uint32_t)__cvta_generic_to_shared(sdyn);
    const int j   = tid & 127;       // B pixel column this thread stages
    const int khi = tid >> 7;        // 0/1 -> k-row parity for B staging

    // warp tile origin
    const int m0w = (wid & 1) * 64;
    const int n0w = (wid >> 1) * 32;
    const int lg  = lane >> 2;
    const int lt  = lane & 3;

    // per-lane pixel coords for B-fragment validity masks
    int xv[4], yv[4];
    #pragma unroll
    for (int nt = 0; nt < 4; nt++) {
        int p = px0 + n0w + nt*8 + lg;
        yv[nt] = p / WW;
        xv[nt] = p - yv[nt]*WW;
    }

    float d[4][4][4];
    #pragma unroll
    for (int mt = 0; mt < 4; mt++)
        #pragma unroll
        for (int nt = 0; nt < 4; nt++)
            #pragma unroll
            for (int q = 0; q < 4; q++) d[mt][nt][q] = 0.f;

    // stage issuer: all A (2 cp16) + B (8 cp4) for k-chunk s, then commit
    auto issue = [&](int s){
        const int slot = s & 3;
        const int t = s >> 4, icc = (s & 15) << 4;
        const int kh = (t*11) >> 5, kw = t - kh*3;       // t/3, t%3
        // A: rows wid and wid+8 of [16 x 128] weight chunk
        const float* ap = wt + ((size_t)(t*256 + icc))*OC + oc0 + lane*4;
        uint32_t ad = sbase + (uint32_t)(slot*STG_W + wid*136 + lane*4)*4;
        cp16(ad,              ap + (size_t)wid*OC);
        cp16(ad + 8*136*4,    ap + (size_t)(wid+8)*OC);
        // B: rows khi+2i of [16 x 128] input chunk, linear shifted address
        const int shift = (kh-1)*WW + (kw-1);
        int obase = (b*ICC + icc + khi)*HW + px0 + j + shift;
        uint32_t bd = sbase + (uint32_t)(slot*STG_W + B_OFF + khi*136 + j)*4;
        #pragma unroll
        for (int i = 0; i < 8; i++) {
            int o = obase + 2*i*HW;
            o = min(max(o, 0), NTOT - 1);                 // clamp; garbage masked later
            cp4(bd + (uint32_t)(2*i*136)*4, in + o);
        }
        cp_commit();
    };

    issue(0); issue(1); issue(2);

    for (int c = 0; c < 144; c++) {
        if (c < 142)       asm volatile("cp.async.wait_group 2;");
        else if (c == 142) asm volatile("cp.async.wait_group 1;");
        else               asm volatile("cp.async.wait_group 0;");
        __syncthreads();                  // stage c visible; slot (c+3)&3 free

        if (c + 3 < 144) issue(c + 3);

        const int slot = c & 3;
        const uint32_t* a_sl = sdyn + slot*STG_W;
        const uint32_t* b_sl = a_sl + B_OFF;
        const int tc = c >> 4;
        const int khc = (tc*11) >> 5, kwc = tc - khc*3;

        uint32_t vm[4];
        #pragma unroll
        for (int nt = 0; nt < 4; nt++) {
            bool v = ((unsigned)(yv[nt] + khc - 1) < HH) &&
                     ((unsigned)(xv[nt] + kwc - 1) < WW);
            vm[nt] = v ? 0xFFFFFFFFu : 0u;
        }

        #pragma unroll
        for (int ks = 0; ks < 2; ks++) {
            const int k0 = ks * 8;
            uint32_t af[4][4], bf[4][2];
            #pragma unroll
            for (int mt = 0; mt < 4; mt++) {
                int mrow = m0w + mt*16 + lg;
                af[mt][0] = a_sl[(k0 + lt    )*136 + mrow    ];
                af[mt][1] = a_sl[(k0 + lt    )*136 + mrow + 8];
                af[mt][2] = a_sl[(k0 + 4 + lt)*136 + mrow    ];
                af[mt][3] = a_sl[(k0 + 4 + lt)*136 + mrow + 8];
            }
            #pragma unroll
            for (int nt = 0; nt < 4; nt++) {
                int ncol = n0w + nt*8 + lg;
                bf[nt][0] = b_sl[(k0 + lt    )*136 + ncol] & vm[nt];
                bf[nt][1] = b_sl[(k0 + 4 + lt)*136 + ncol] & vm[nt];
            }
            #pragma unroll
            for (int mt = 0; mt < 4; mt++)
                #pragma unroll
                for (int nt = 0; nt < 4; nt++)
                    mma_tf32(d[mt][nt], af[mt], bf[nt]);
        }
    }
    __syncthreads();

    // epilogue: BN + ReLU + store
    #pragma unroll
    for (int mt = 0; mt < 4; mt++) {
        int r0 = m0w + mt*16 + lg;
        float sc0 = sc_s[r0],     sh0 = sh_s[r0];
        float sc1 = sc_s[r0 + 8], sh1 = sh_s[r0 + 8];
        float* ob0 = out + ((size_t)(b*OC + oc0 + r0    ) * HW) + px0;
        float* ob1 = out + ((size_t)(b*OC + oc0 + r0 + 8) * HW) + px0;
        #pragma unroll
        for (int nt = 0; nt < 4; nt++) {
            int cc = n0w + nt*8 + lt*2;
            float v0 = d[mt][nt][0] * sc0 + sh0;
            float v1 = d[mt][nt][1] * sc0 + sh0;
            float v2 = d[mt][nt][2] * sc1 + sh1;
            float v3 = d[mt][nt][3] * sc1 + sh1;
            *(float2*)(ob0 + cc) = make_float2(v0 > 0.f ? v0 : 0.f, v1 > 0.f ? v1 : 0.f);
            *(float2*)(ob1 + cc) = make_float2(v2 > 0.f ? v2 : 0.f, v3 > 0.f ? v3 : 0.f);
        }
    }
}

// ---------------------------------------------------------------------------
// 1x1 conv to one channel + head nonlinearity (mode 0: depth, 1: softplus)
// ---------------------------------------------------------------------------
__global__ __launch_bounds__(256) void head1x1(
    const float* __restrict__ in, const float* __restrict__ w,
    const float* __restrict__ bias, float* __restrict__ out, int C, int mode)
{
    __shared__ float sw[256];
    if (threadIdx.x < C) sw[threadIdx.x] = w[threadIdx.x];
    __syncthreads();

    int idx = blockIdx.x * 256 + threadIdx.x;
    int b = idx / HW; int p = idx - b*HW;
    const float* base = in + (size_t)b*C*HW + p;
    float acc = bias[0];
#pragma unroll 8
    for (int c = 0; c < C; c++) acc += base[(size_t)c*HW] * sw[c];

    float res;
    if (mode == 0) {
        float disp = 1.f / (1.f + expf(-acc));
        res = 1.f / (0.01f + 9.99f * disp);
    } else {
        res = acc > 20.f ? acc : log1pf(expf(acc));
    }
    out[idx] = res;
}

// ---------------------------------------------------------------------------
// Per-box lower median via exact 32-bit radix select.
// ---------------------------------------------------------------------------
__global__ __launch_bounds__(256) void box_median(
    const float* __restrict__ depth, const int* __restrict__ bboxes,
    float* __restrict__ out)
{
    const int bi = blockIdx.x;
    const int b = bi >> 6;
    const int tid = threadIdx.x;
    const int* box = bboxes + (size_t)bi * 4;

    int x1 = max(box[0], 0), y1 = max(box[1], 0);
    int x2 = min(box[2], WW), y2 = min(box[3], HH);
    int wdt = x2 - x1, hgt = y2 - y1;
    if (wdt <= 0 || hgt <= 0) {
        if (tid == 0) out[bi] = 0.f;
        return;
    }
    const int k = wdt * hgt;
    int r = (k - 1) >> 1;

    __shared__ unsigned hist[256];
    const float* dimg = depth + (size_t)b * HW;
    unsigned prefix = 0;

    for (int pass = 0; pass < 4; ++pass) {
        int shift = 24 - 8*pass;
        hist[tid] = 0;
        __syncthreads();
        unsigned pmask = (pass == 0) ? 0u : (0xFFFFFFFFu << (shift + 8));
        for (int e = tid; e < k; e += 256) {
            int y = y1 + e / wdt, x = x1 + e % wdt;
            unsigned bits = __float_as_uint(dimg[y*WW + x]);
            if ((bits & pmask) == prefix)
                atomicAdd(&hist[(bits >> shift) & 0xFF], 1u);
        }
        __syncthreads();
        unsigned cum = 0; int bin = -1;
        for (int i = 0; i < 256; i++) {
            unsigned h = hist[i];
            if (bin < 0 && r < (int)(cum + h)) { bin = i; r -= (int)cum; }
            cum += h;
        }
        prefix |= ((unsigned)bin) << shift;
        __syncthreads();
    }
    if (tid == 0) out[bi] = __uint_as_float(prefix);
}

// ---------------------------------------------------------------------------
extern "C" void kernel_launch(void* const* d_in, const int* in_sizes, int n_in,
                              void* d_out, int out_size)
{
    const float* features = (const float*)d_in[0];
    const int*   bboxes   = (const int*)  d_in[1];
    const float* w1  = (const float*)d_in[2];
    const float* b1  = (const float*)d_in[3];
    const float* g1  = (const float*)d_in[4];
    const float* be1 = (const float*)d_in[5];
    const float* m1  = (const float*)d_in[6];
    const float* v1  = (const float*)d_in[7];
    const float* w2  = (const float*)d_in[8];
    const float* b2  = (const float*)d_in[9];
    const float* g2  = (const float*)d_in[10];
    const float* be2 = (const float*)d_in[11];
    const float* m2  = (const float*)d_in[12];
    const float* v2  = (const float*)d_in[13];
    const float* w3  = (const float*)d_in[14];
    const float* b3  = (const float*)d_in[15];
    const float* uw1 = (const float*)d_in[16];
    const float* ub1 = (const float*)d_in[17];
    const float* uw2 = (const float*)d_in[18];
    const float* ub2 = (const float*)d_in[19];

    float* out = (float*)d_out;

    float *h1, *h2, *u1, *w1t, *w2t, *uwt;
    cudaGetSymbolAddress((void**)&h1,  g_h1);
    cudaGetSymbolAddress((void**)&h2,  g_h2);
    cudaGetSymbolAddress((void**)&u1,  g_u1);
    cudaGetSymbolAddress((void**)&w1t, g_w1t);
    cudaGetSymbolAddress((void**)&w2t, g_w2t);
    cudaGetSymbolAddress((void**)&uwt, g_uwt);

    cudaFuncSetAttribute(conv3x3_mma,
        cudaFuncAttributeMaxDynamicSharedMemorySize, SMEM_DYN);

    // weight layout transforms
    wtrans<<<(9*256*256 + 255)/256, 256>>>(w1,  w1t, 256);
    wtrans<<<(9*256*256 + 255)/256, 256>>>(w2,  w2t, 256);
    wtrans<<<(9*256*128 + 255)/256, 256>>>(uw1, uwt, 128);

    dim3 g256(120, 2, 8);   // 120 pixel tiles, 2 oc-tiles, 8 batch
    dim3 g128(120, 1, 8);

    // depth head
    conv3x3_mma<<<g256, 256, SMEM_DYN>>>(features, w1t, b1, g1, be1, m1, v1, h1, 256, 1);
    conv3x3_mma<<<g256, 256, SMEM_DYN>>>(h1,       w2t, b2, g2, be2, m2, v2, h2, 256, 1);
    head1x1<<<480, 256>>>(h2, w3, b3, out, 256, 0);                 // depth

    // uncertainty head
    conv3x3_mma<<<g128, 256, SMEM_DYN>>>(features, uwt, ub1,
        (const float*)0, (const float*)0, (const float*)0, (const float*)0, u1, 128, 0);
    head1x1<<<480, 256>>>(u1, uw2, ub2, out + 122880, 128, 1);      // uncertainty

    // per-box medians from depth
    box_median<<<512, 256>>>(out, bboxes, out + 245760);            // obj depths
}